// round 1
// baseline (speedup 1.0000x reference)
#include <cuda_runtime.h>
#include <cuda_bf16.h>

#define FEAT 384
#define FEAT4 (FEAT / 4)   // 96 float4 per row
#define ALPHA 0.2f

__global__ void zero_out_kernel(float* out) {
    if (threadIdx.x == 0 && blockIdx.x == 0) out[0] = 0.0f;
}

__global__ __launch_bounds__(256) void triplet_kernel(
    const float4* __restrict__ anchor,
    const float4* __restrict__ positive,
    const float4* __restrict__ negative,
    const float*  __restrict__ W,
    float* __restrict__ out,
    int B)
{
    __shared__ float expw[FEAT];
    __shared__ float block_sum;

    // Precompute exp(W) once per block.
    for (int i = threadIdx.x; i < FEAT; i += blockDim.x)
        expw[i] = expf(W[i]);
    if (threadIdx.x == 0) block_sum = 0.0f;
    __syncthreads();

    const int lane  = threadIdx.x & 31;
    const int warp  = threadIdx.x >> 5;
    const int wpb   = blockDim.x >> 5;
    const int gwarp = blockIdx.x * wpb + warp;
    const int nwarp = gridDim.x * wpb;

    // Preload this lane's 3 float4 of exp(W) into registers (reused every row).
    float4 wv[3];
    #pragma unroll
    for (int j = 0; j < 3; j++) {
        const int idx = j * 32 + lane;          // float4 index within row
        wv[j] = *reinterpret_cast<const float4*>(&expw[idx * 4]);
    }

    float acc = 0.0f;   // only meaningful on lane 0

    for (int row = gwarp; row < B; row += nwarp) {
        const float4* ar = anchor   + (long long)row * FEAT4;
        const float4* pr = positive + (long long)row * FEAT4;
        const float4* nr = negative + (long long)row * FEAT4;

        float d = 0.0f;   // partial of (D_pos - D_neg)
        #pragma unroll
        for (int j = 0; j < 3; j++) {
            const int idx = j * 32 + lane;
            const float4 av = __ldg(&ar[idx]);
            const float4 pv = __ldg(&pr[idx]);
            const float4 nv = __ldg(&nr[idx]);

            float dp, dn;
            dp = av.x - pv.x; dn = av.x - nv.x; d += wv[j].x * (dp * dp - dn * dn);
            dp = av.y - pv.y; dn = av.y - nv.y; d += wv[j].y * (dp * dp - dn * dn);
            dp = av.z - pv.z; dn = av.z - nv.z; d += wv[j].z * (dp * dp - dn * dn);
            dp = av.w - pv.w; dn = av.w - nv.w; d += wv[j].w * (dp * dp - dn * dn);
        }

        // Warp reduction of the per-lane partials.
        #pragma unroll
        for (int off = 16; off > 0; off >>= 1)
            d += __shfl_xor_sync(0xFFFFFFFFu, d, off);

        if (lane == 0)
            acc += fmaxf(d + ALPHA, 0.0f);
    }

    if (lane == 0)
        atomicAdd(&block_sum, acc);
    __syncthreads();

    if (threadIdx.x == 0)
        atomicAdd(out, block_sum * (1.0f / (float)B));
}

extern "C" void kernel_launch(void* const* d_in, const int* in_sizes, int n_in,
                              void* d_out, int out_size) {
    const float4* anchor   = (const float4*)d_in[0];
    const float4* positive = (const float4*)d_in[1];
    const float4* negative = (const float4*)d_in[2];
    const float*  W        = (const float*)d_in[3];
    float* out = (float*)d_out;

    const int B = in_sizes[0] / FEAT;   // 131072

    zero_out_kernel<<<1, 32>>>(out);

    const int threads = 256;
    const int blocks  = 1184;           // 148 SMs * 8 blocks, grid-stride over rows
    triplet_kernel<<<blocks, threads>>>(anchor, positive, negative, W, out, B);
}